// round 1
// baseline (speedup 1.0000x reference)
#include <cuda_runtime.h>
#include <math.h>

#define CIN  2048
#define CHID 1024
#define CEMB 256
#define BB   4
#define TT   2048

// ---------------- scratch (allocation-free: device globals) ----------------
__device__ float d_theta[BB * TT * CHID];   // x @ theta_w^T   (B,T,H)
__device__ float d_phi  [BB * TT * CHID];   // x @ phi_w^T     (B,T,H)
__device__ float d_g    [BB * TT * CHID];   // x @ g_w^T       (B,T,H)
__device__ float d_y    [BB * TT * CHID];   // y^T             (B,T(s),H)
__device__ float d_nssm [BB * TT * TT];     // softmax(x x^T)  (B,T,T)
__device__ float d_att  [BB * TT * TT];     // softmax(phi th) (B,T,T)
__device__ float d_moca [BB * TT * TT];     // (B,T,T)
__device__ float d_wz   [BB * TT * CIN];    // (wz + x)^T      (B,T,C)

// ---------------- generic 64x64x16 tiled SGEMM ----------------
// MODE 0 (NT): C[m,n] = sum_k A[m*lda+k] * B[n*ldb+k]
// MODE 1 (TN): C[m,n] = sum_k A[k*lda+m] * B[k*ldb+n]
// optional bias[n], optional add[m*ldc+n]. Batched via blockIdx.z + strides.
// All M,N divisible by 64, K divisible by 16 for this problem.
template <int MODE>
__global__ __launch_bounds__(256) void gemm64(
    const float* __restrict__ A, const float* __restrict__ B,
    float* __restrict__ C,
    int K, int lda, int ldb, int ldc,
    long sA, long sB, long sC,
    const float* __restrict__ bias,
    const float* __restrict__ add)
{
    const int bz = blockIdx.z;
    A += (long)bz * sA;
    B += (long)bz * sB;
    C += (long)bz * sC;
    if (add) add += (long)bz * sC;

    __shared__ float As[16][68];
    __shared__ float Bs[16][68];

    const int m0 = blockIdx.y * 64;
    const int n0 = blockIdx.x * 64;
    const int tid = threadIdx.x;          // 256 threads
    const int tm = tid / 16;              // 0..15
    const int tn = tid % 16;              // 0..15

    float acc[4][4];
    #pragma unroll
    for (int i = 0; i < 4; i++)
        #pragma unroll
        for (int j = 0; j < 4; j++) acc[i][j] = 0.0f;

    for (int k0 = 0; k0 < K; k0 += 16) {
        #pragma unroll
        for (int i = 0; i < 4; i++) {
            int lin = tid + i * 256;
            if (MODE == 0) {
                int m = lin >> 4, k = lin & 15;
                As[k][m] = A[(long)(m0 + m) * lda + (k0 + k)];
            } else {
                int k = lin >> 6, m = lin & 63;
                As[k][m] = A[(long)(k0 + k) * lda + (m0 + m)];
            }
        }
        #pragma unroll
        for (int i = 0; i < 4; i++) {
            int lin = tid + i * 256;
            if (MODE == 0) {
                int n = lin >> 4, k = lin & 15;
                Bs[k][n] = B[(long)(n0 + n) * ldb + (k0 + k)];
            } else {
                int k = lin >> 6, n = lin & 63;
                Bs[k][n] = B[(long)(k0 + k) * ldb + (n0 + n)];
            }
        }
        __syncthreads();

        #pragma unroll
        for (int kk = 0; kk < 16; kk++) {
            float a[4], b[4];
            #pragma unroll
            for (int i = 0; i < 4; i++) a[i] = As[kk][tm * 4 + i];
            #pragma unroll
            for (int j = 0; j < 4; j++) b[j] = Bs[kk][tn * 4 + j];
            #pragma unroll
            for (int i = 0; i < 4; i++)
                #pragma unroll
                for (int j = 0; j < 4; j++)
                    acc[i][j] = fmaf(a[i], b[j], acc[i][j]);
        }
        __syncthreads();
    }

    #pragma unroll
    for (int i = 0; i < 4; i++) {
        const int m = m0 + tm * 4 + i;
        #pragma unroll
        for (int j = 0; j < 4; j++) {
            const int n = n0 + tn * 4 + j;
            float v = acc[i][j];
            if (bias) v += bias[n];
            if (add)  v += add[(long)m * ldc + n];
            C[(long)m * ldc + n] = v;
        }
    }
}

// ---------------- row softmax over 2048 elements, in place ----------------
__global__ __launch_bounds__(256) void softmax_rows(float* __restrict__ p)
{
    const long row = blockIdx.x;
    float* r = p + row * (long)TT;
    const int tid = threadIdx.x;

    float v[8];
    float mx = -3.0e38f;
    #pragma unroll
    for (int i = 0; i < 8; i++) {
        v[i] = r[tid + i * 256];
        mx = fmaxf(mx, v[i]);
    }
    __shared__ float sm[256];
    sm[tid] = mx; __syncthreads();
    #pragma unroll
    for (int s = 128; s > 0; s >>= 1) {
        if (tid < s) sm[tid] = fmaxf(sm[tid], sm[tid + s]);
        __syncthreads();
    }
    mx = sm[0]; __syncthreads();

    float sum = 0.0f;
    #pragma unroll
    for (int i = 0; i < 8; i++) { v[i] = expf(v[i] - mx); sum += v[i]; }
    sm[tid] = sum; __syncthreads();
    #pragma unroll
    for (int s = 128; s > 0; s >>= 1) {
        if (tid < s) sm[tid] += sm[tid + s];
        __syncthreads();
    }
    const float inv = 1.0f / sm[0];
    #pragma unroll
    for (int i = 0; i < 8; i++) r[tid + i * 256] = v[i] * inv;
}

// ---------------- cat(axis=0).reshape(B,2,T,T) pairing + combine + softmax --
// moca[0] = sm(r0*nssm[0] + r1*nssm[1] + rb)
// moca[1] = sm(r0*nssm[2] + r1*nssm[3] + rb)
// moca[2] = sm(r0*att [0] + r1*att [1] + rb)
// moca[3] = sm(r0*att [2] + r1*att [3] + rb)
__global__ __launch_bounds__(256) void combine_softmax(
    const float* __restrict__ nssm, const float* __restrict__ att,
    float* __restrict__ moca,
    const float* __restrict__ rou_w, const float* __restrict__ rou_b)
{
    const long row = blockIdx.x;           // 0 .. B*T-1
    const int b = (int)(row / TT);
    const long t = row % TT;
    const float r0 = rou_w[0], r1 = rou_w[1], rb = rou_b[0];

    const float* src = (b < 2) ? nssm : att;
    const int base = (b & 1) * 2;
    const float* pa = src + ((long)base * TT + t) * TT;
    const float* pb = src + ((long)(base + 1) * TT + t) * TT;
    float* w = moca + row * (long)TT;

    const int tid = threadIdx.x;
    float v[8];
    float mx = -3.0e38f;
    #pragma unroll
    for (int i = 0; i < 8; i++) {
        const int c = tid + i * 256;
        v[i] = r0 * pa[c] + r1 * pb[c] + rb;
        mx = fmaxf(mx, v[i]);
    }
    __shared__ float sm[256];
    sm[tid] = mx; __syncthreads();
    #pragma unroll
    for (int s = 128; s > 0; s >>= 1) {
        if (tid < s) sm[tid] = fmaxf(sm[tid], sm[tid + s]);
        __syncthreads();
    }
    mx = sm[0]; __syncthreads();

    float sum = 0.0f;
    #pragma unroll
    for (int i = 0; i < 8; i++) { v[i] = expf(v[i] - mx); sum += v[i]; }
    sm[tid] = sum; __syncthreads();
    #pragma unroll
    for (int s = 128; s > 0; s >>= 1) {
        if (tid < s) sm[tid] += sm[tid + s];
        __syncthreads();
    }
    const float inv = 1.0f / sm[0];
    #pragma unroll
    for (int i = 0; i < 8; i++) w[tid + i * 256] = v[i] * inv;
}

// ---------------- launch ----------------
extern "C" void kernel_launch(void* const* d_in, const int* in_sizes, int n_in,
                              void* d_out, int out_size)
{
    (void)in_sizes; (void)n_in; (void)out_size;
    const float* x       = (const float*)d_in[0];
    const float* theta_w = (const float*)d_in[1];
    const float* theta_b = (const float*)d_in[2];
    const float* phi_w   = (const float*)d_in[3];
    const float* phi_b   = (const float*)d_in[4];
    const float* g_w     = (const float*)d_in[5];
    const float* g_b     = (const float*)d_in[6];
    const float* rou_w   = (const float*)d_in[7];
    const float* rou_b   = (const float*)d_in[8];
    const float* w_w     = (const float*)d_in[9];
    const float* w_b     = (const float*)d_in[10];
    const float* emb_w   = (const float*)d_in[11];
    const float* emb_b   = (const float*)d_in[12];
    float* out = (float*)d_out;

    float *p_theta, *p_phi, *p_g, *p_y, *p_nssm, *p_att, *p_moca, *p_wz;
    cudaGetSymbolAddress((void**)&p_theta, d_theta);
    cudaGetSymbolAddress((void**)&p_phi,   d_phi);
    cudaGetSymbolAddress((void**)&p_g,     d_g);
    cudaGetSymbolAddress((void**)&p_y,     d_y);
    cudaGetSymbolAddress((void**)&p_nssm,  d_nssm);
    cudaGetSymbolAddress((void**)&p_att,   d_att);
    cudaGetSymbolAddress((void**)&p_moca,  d_moca);
    cudaGetSymbolAddress((void**)&p_wz,    d_wz);

    const int MT = BB * TT;  // 8192 rows across batches

    // Projections: (B*T, C_IN) @ W^T -> (B*T, C_HID)
    {
        dim3 grid(CHID / 64, MT / 64, 1);
        gemm64<0><<<grid, 256>>>(x, theta_w, p_theta, CIN, CIN, CIN, CHID,
                                 0, 0, 0, theta_b, nullptr);
        gemm64<0><<<grid, 256>>>(x, phi_w,   p_phi,   CIN, CIN, CIN, CHID,
                                 0, 0, 0, phi_b, nullptr);
        gemm64<0><<<grid, 256>>>(x, g_w,     p_g,     CIN, CIN, CIN, CHID,
                                 0, 0, 0, g_b, nullptr);
    }

    // Gram: nssm_logits[b] = x[b] @ x[b]^T  (T,T), K=C_IN
    {
        dim3 grid(TT / 64, TT / 64, BB);
        gemm64<0><<<grid, 256>>>(x, x, p_nssm, CIN, CIN, CIN, TT,
                                 (long)TT * CIN, (long)TT * CIN, (long)TT * TT,
                                 nullptr, nullptr);
    }
    softmax_rows<<<BB * TT, 256>>>(p_nssm);

    // att_logits[b] = phi[b] @ theta[b]^T  (T,T), K=C_HID
    {
        dim3 grid(TT / 64, TT / 64, BB);
        gemm64<0><<<grid, 256>>>(p_phi, p_theta, p_att, CHID, CHID, CHID, TT,
                                 (long)TT * CHID, (long)TT * CHID, (long)TT * TT,
                                 nullptr, nullptr);
    }
    softmax_rows<<<BB * TT, 256>>>(p_att);

    // moca (with the cat/reshape batch interleave)
    combine_softmax<<<BB * TT, 256>>>(p_nssm, p_att, p_moca, rou_w, rou_b);

    // y^T[b] = moca[b]^T @ g[b]   (TN): C[s,h] = sum_t moca[t,s] * g[t,h]
    {
        dim3 grid(CHID / 64, TT / 64, BB);
        gemm64<1><<<grid, 256>>>(p_moca, p_g, p_y, TT, TT, CHID, CHID,
                                 (long)TT * TT, (long)TT * CHID, (long)TT * CHID,
                                 nullptr, nullptr);
    }

    // wz^T = y^T @ w_w^T + w_b + x   (B*T, C_IN), K=C_HID
    {
        dim3 grid(CIN / 64, MT / 64, 1);
        gemm64<0><<<grid, 256>>>(p_y, w_w, p_wz, CHID, CHID, CHID, CIN,
                                 0, 0, 0, w_b, x);
    }

    // out = wz^T @ emb_w^T + emb_b   (B*T, 256), K=C_IN
    {
        dim3 grid(CEMB / 64, MT / 64, 1);
        gemm64<0><<<grid, 256>>>(p_wz, emb_w, out, CIN, CIN, CIN, CEMB,
                                 0, 0, 0, emb_b, nullptr);
    }
}

// round 4
// speedup vs baseline: 3.2736x; 3.2736x over previous
#include <cuda_runtime.h>
#include <math.h>
#include <stdint.h>

#define CIN  2048
#define CHID 1024
#define CEMB 256
#define BB   4
#define TT   2048
#define MTOT (BB * TT)   // 8192

// ---------------- scratch (device globals; allocation-free) ----------------
#define F32_ARR(name, n) __device__ uint4 name[(n) / 4]
F32_ARR(g_theta, MTOT * CHID);
F32_ARR(g_phi,   MTOT * CHID);
F32_ARR(g_gT,    BB * CHID * TT);
F32_ARR(g_y2,    MTOT * CHID);
F32_ARR(g_wz,    MTOT * CIN);
F32_ARR(g_nssm,  BB * TT * TT);
F32_ARR(g_att,   BB * TT * TT);
F32_ARR(g_moca,  BB * TT * TT);
F32_ARR(g_mT,    BB * TT * TT);

// ---------------- helpers ----------------
__device__ __forceinline__ uint32_t smem_u32(const void* p) {
    uint32_t a;
    asm("{ .reg .u64 t; cvta.to.shared.u64 t, %1; cvt.u32.u64 %0, t; }" : "=r"(a) : "l"(p));
    return a;
}
__device__ __forceinline__ uint32_t f2tf(float f) {
    uint32_t u;
    asm("cvt.rna.tf32.f32 %0, %1;" : "=r"(u) : "f"(f));
    return u;
}
__device__ __forceinline__ void mma8(float* c, const uint32_t* a, const uint32_t* b) {
    asm volatile(
        "mma.sync.aligned.m16n8k8.row.col.f32.tf32.tf32.f32 "
        "{%0,%1,%2,%3}, {%4,%5,%6,%7}, {%8,%9}, {%0,%1,%2,%3};"
        : "+f"(c[0]), "+f"(c[1]), "+f"(c[2]), "+f"(c[3])
        : "r"(a[0]), "r"(a[1]), "r"(a[2]), "r"(a[3]), "r"(b[0]), "r"(b[1]));
}

// ---------------- tf32 mma.sync GEMM: C[m,n] = sum_k A[m,k]*B[n,k] ----------
// Tile 128(M) x 128(N) x 32(K). 256 threads = 8 warps in 4(M) x 2(N).
// SPLIT=0: single-pass tf32 (rna).  SPLIT=1: tf32x2 emulation (3 combos).
#define SROW 36                       // padded row stride in floats (conflict-free)
#define STG  (128 * SROW)             // 4608 floats per operand stage
#define GSM_FLOATS (4 * STG)          // A0,A1,B0,B1
#define GSM_BYTES  (GSM_FLOATS * 4)   // 73728

template <int SPLIT>
__global__ __launch_bounds__(256) void gemm_mma(
    const float* __restrict__ A, const float* __restrict__ B,
    float* __restrict__ C,
    const float* __restrict__ biasCol, const float* __restrict__ biasRow,
    const float* __restrict__ addF,
    int K, int lda, int ldb, int ldc,
    long long sA, long long sB, long long sC)
{
    extern __shared__ float sm[];
    const int tid = threadIdx.x;
    const int lane = tid & 31, warp = tid >> 5;
    const int warpM = (warp >> 1) * 32, warpN = (warp & 1) * 64;
    const int lr = lane >> 2, lc = lane & 3;

    const long long bz = blockIdx.z;
    A += bz * sA; B += bz * sB;
    const long long co = bz * sC;
    C += co;
    if (addF) addF += co;

    const int m0 = blockIdx.y * 128, n0 = blockIdx.x * 128;
    const uint32_t sb = smem_u32(sm);

    float acc[2][8][4];
    #pragma unroll
    for (int i = 0; i < 2; i++)
        #pragma unroll
        for (int j = 0; j < 8; j++)
            #pragma unroll
            for (int q = 0; q < 4; q++) acc[i][j][q] = 0.0f;

    const int NK = K >> 5;

    // stage loader: 128 rows x 32 floats per operand, 16B cp.async chunks
    auto issue = [&](int st, int k0) {
        #pragma unroll
        for (int i = 0; i < 4; i++) {
            const int id = i * 256 + tid;
            const int row = id >> 3;
            const int c4 = (id & 7) * 4;
            const float* ga = A + (size_t)(m0 + row) * lda + k0 + c4;
            const float* gb = B + (size_t)(n0 + row) * ldb + k0 + c4;
            const uint32_t da = sb + (uint32_t)(st * STG + row * SROW + c4) * 4u;
            const uint32_t db = sb + (uint32_t)(2 * STG + st * STG + row * SROW + c4) * 4u;
            asm volatile("cp.async.ca.shared.global [%0], [%1], 16;" :: "r"(da), "l"(ga));
            asm volatile("cp.async.ca.shared.global [%0], [%1], 16;" :: "r"(db), "l"(gb));
        }
        asm volatile("cp.async.commit_group;" ::: "memory");
    };

    issue(0, 0);
    for (int kc = 0; kc < NK; kc++) {
        if (kc + 1 < NK) {
            issue((kc + 1) & 1, (kc + 1) << 5);
            asm volatile("cp.async.wait_group 1;" ::: "memory");
        } else {
            asm volatile("cp.async.wait_group 0;" ::: "memory");
        }
        __syncthreads();

        const float* as = sm + (kc & 1) * STG;
        const float* bs = sm + 2 * STG + (kc & 1) * STG;

        #pragma unroll
        for (int kk = 0; kk < 4; kk++) {
            uint32_t ah[2][4], al[2][4];
            #pragma unroll
            for (int mt = 0; mt < 2; mt++) {
                const float* pa = as + (warpM + mt * 16 + lr) * SROW + kk * 8 + lc;
                const float f0 = pa[0], f1 = pa[8 * SROW], f2 = pa[4], f3 = pa[8 * SROW + 4];
                ah[mt][0] = f2tf(f0); ah[mt][1] = f2tf(f1);
                ah[mt][2] = f2tf(f2); ah[mt][3] = f2tf(f3);
                if (SPLIT) {
                    al[mt][0] = f2tf(f0 - __uint_as_float(ah[mt][0]));
                    al[mt][1] = f2tf(f1 - __uint_as_float(ah[mt][1]));
                    al[mt][2] = f2tf(f2 - __uint_as_float(ah[mt][2]));
                    al[mt][3] = f2tf(f3 - __uint_as_float(ah[mt][3]));
                }
            }
            #pragma unroll
            for (int nt = 0; nt < 8; nt++) {
                const float* pb = bs + (warpN + nt * 8 + lr) * SROW + kk * 8 + lc;
                const float g0 = pb[0], g1 = pb[4];
                uint32_t bh[2], bl[2];
                bh[0] = f2tf(g0); bh[1] = f2tf(g1);
                if (SPLIT) {
                    bl[0] = f2tf(g0 - __uint_as_float(bh[0]));
                    bl[1] = f2tf(g1 - __uint_as_float(bh[1]));
                }
                #pragma unroll
                for (int mt = 0; mt < 2; mt++) {
                    mma8(acc[mt][nt], ah[mt], bh);
                    if (SPLIT) {
                        mma8(acc[mt][nt], ah[mt], bl);
                        mma8(acc[mt][nt], al[mt], bh);
                    }
                }
            }
        }
        __syncthreads();
    }

    // epilogue
    #pragma unroll
    for (int mt = 0; mt < 2; mt++) {
        #pragma unroll
        for (int nt = 0; nt < 8; nt++) {
            const int r0 = m0 + warpM + mt * 16 + lr;
            const int r1 = r0 + 8;
            const int cx = n0 + warpN + nt * 8 + 2 * lc;
            float v0 = acc[mt][nt][0], v1 = acc[mt][nt][1];
            float v2 = acc[mt][nt][2], v3 = acc[mt][nt][3];
            if (biasCol) {
                const float b0 = biasCol[cx], b1 = biasCol[cx + 1];
                v0 += b0; v1 += b1; v2 += b0; v3 += b1;
            }
            if (biasRow) { v0 += biasRow[r0]; v1 += biasRow[r0]; v2 += biasRow[r1]; v3 += biasRow[r1]; }
            const size_t o0 = (size_t)r0 * ldc + cx;
            const size_t o1 = (size_t)r1 * ldc + cx;
            if (addF) { v0 += addF[o0]; v1 += addF[o0 + 1]; v2 += addF[o1]; v3 += addF[o1 + 1]; }
            float2 w0; w0.x = v0; w0.y = v1;
            float2 w1; w1.x = v2; w1.y = v3;
            *(float2*)&C[o0] = w0;
            *(float2*)&C[o1] = w1;
        }
    }
}

// ---------------- batched fp32 transpose: out[c][r] = in[r][c] ----------------
__global__ __launch_bounds__(256) void transpose_f32(
    const float* __restrict__ in, float* __restrict__ outp,
    int R, int C, long long sIn, long long sOut)
{
    __shared__ float t[32][33];
    const long long b = blockIdx.z;
    in += b * sIn; outp += b * sOut;
    const int c0 = blockIdx.x * 32, r0 = blockIdx.y * 32;
    const int tx = threadIdx.x, ty = threadIdx.y;
    #pragma unroll
    for (int j = 0; j < 4; j++)
        t[ty + j * 8][tx] = in[(size_t)(r0 + ty + j * 8) * C + (c0 + tx)];
    __syncthreads();
    #pragma unroll
    for (int j = 0; j < 4; j++)
        outp[(size_t)(c0 + ty + j * 8) * R + (r0 + tx)] = t[tx][ty + j * 8];
}

// ---------------- row softmax over 2048 elements, in place ----------------
__global__ __launch_bounds__(256) void softmax_rows(float* __restrict__ p)
{
    const long long row = blockIdx.x;
    float* r = p + row * (long long)TT;
    const int tid = threadIdx.x;
    float v[8];
    float mx = -3.0e38f;
    #pragma unroll
    for (int i = 0; i < 8; i++) { v[i] = r[tid + i * 256]; mx = fmaxf(mx, v[i]); }
    __shared__ float sm[256];
    sm[tid] = mx; __syncthreads();
    #pragma unroll
    for (int s = 128; s > 0; s >>= 1) {
        if (tid < s) sm[tid] = fmaxf(sm[tid], sm[tid + s]);
        __syncthreads();
    }
    mx = sm[0]; __syncthreads();
    float sum = 0.0f;
    #pragma unroll
    for (int i = 0; i < 8; i++) { v[i] = expf(v[i] - mx); sum += v[i]; }
    sm[tid] = sum; __syncthreads();
    #pragma unroll
    for (int s = 128; s > 0; s >>= 1) {
        if (tid < s) sm[tid] += sm[tid + s];
        __syncthreads();
    }
    const float inv = 1.0f / sm[0];
    #pragma unroll
    for (int i = 0; i < 8; i++) r[tid + i * 256] = v[i] * inv;
}

// ------- cat(axis=0).reshape(B,2,T,T) pairing + combine + softmax ----------
__global__ __launch_bounds__(256) void combine_softmax(
    const float* __restrict__ nssm, const float* __restrict__ att,
    float* __restrict__ moca,
    const float* __restrict__ rou_w, const float* __restrict__ rou_b)
{
    const long long row = blockIdx.x;           // 0 .. B*T-1
    const int b = (int)(row / TT);
    const long long t = row % TT;
    const float r0 = rou_w[0], r1 = rou_w[1], rb = rou_b[0];

    const float* src = (b < 2) ? nssm : att;
    const int base = (b & 1) * 2;
    const float* pa = src + ((long long)base * TT + t) * TT;
    const float* pb = src + ((long long)(base + 1) * TT + t) * TT;
    float* w = moca + row * (long long)TT;

    const int tid = threadIdx.x;
    float v[8];
    float mx = -3.0e38f;
    #pragma unroll
    for (int i = 0; i < 8; i++) {
        const int c = tid + i * 256;
        v[i] = r0 * pa[c] + r1 * pb[c] + rb;
        mx = fmaxf(mx, v[i]);
    }
    __shared__ float sm[256];
    sm[tid] = mx; __syncthreads();
    #pragma unroll
    for (int s = 128; s > 0; s >>= 1) {
        if (tid < s) sm[tid] = fmaxf(sm[tid], sm[tid + s]);
        __syncthreads();
    }
    mx = sm[0]; __syncthreads();
    float sum = 0.0f;
    #pragma unroll
    for (int i = 0; i < 8; i++) { v[i] = expf(v[i] - mx); sum += v[i]; }
    sm[tid] = sum; __syncthreads();
    #pragma unroll
    for (int s = 128; s > 0; s >>= 1) {
        if (tid < s) sm[tid] += sm[tid + s];
        __syncthreads();
    }
    const float inv = 1.0f / sm[0];
    #pragma unroll
    for (int i = 0; i < 8; i++) w[tid + i * 256] = v[i] * inv;
}

// ---------------- launch ----------------
#define SYMF(p, s)  do { void* _t; cudaGetSymbolAddress(&_t, s); p = (float*)_t; } while (0)

extern "C" void kernel_launch(void* const* d_in, const int* in_sizes, int n_in,
                              void* d_out, int out_size)
{
    (void)in_sizes; (void)n_in; (void)out_size;
    const float* x       = (const float*)d_in[0];
    const float* theta_w = (const float*)d_in[1];
    const float* theta_b = (const float*)d_in[2];
    const float* phi_w   = (const float*)d_in[3];
    const float* phi_b   = (const float*)d_in[4];
    const float* g_w     = (const float*)d_in[5];
    const float* g_b     = (const float*)d_in[6];
    const float* rou_w   = (const float*)d_in[7];
    const float* rou_b   = (const float*)d_in[8];
    const float* w_w     = (const float*)d_in[9];
    const float* w_b     = (const float*)d_in[10];
    const float* emb_w   = (const float*)d_in[11];
    const float* emb_b   = (const float*)d_in[12];
    float* out = (float*)d_out;

    float *theta, *phi, *gT, *y2, *wz, *nssm, *att, *moca, *mT;
    SYMF(theta, g_theta); SYMF(phi, g_phi); SYMF(gT, g_gT);
    SYMF(y2, g_y2); SYMF(wz, g_wz);
    SYMF(nssm, g_nssm); SYMF(att, g_att); SYMF(moca, g_moca); SYMF(mT, g_mT);

    cudaFuncSetAttribute(gemm_mma<0>, cudaFuncAttributeMaxDynamicSharedMemorySize, GSM_BYTES);
    cudaFuncSetAttribute(gemm_mma<1>, cudaFuncAttributeMaxDynamicSharedMemorySize, GSM_BYTES);

    // 1. theta = x @ theta_w^T + theta_b   (M=8192, N=1024, K=2048) — FAST
    gemm_mma<0><<<dim3(CHID / 128, MTOT / 128, 1), 256, GSM_BYTES>>>(
        x, theta_w, theta, theta_b, nullptr, nullptr,
        CIN, CIN, CIN, CHID, 0, 0, 0);
    // 2. phi — FAST
    gemm_mma<0><<<dim3(CHID / 128, MTOT / 128, 1), 256, GSM_BYTES>>>(
        x, phi_w, phi, phi_b, nullptr, nullptr,
        CIN, CIN, CIN, CHID, 0, 0, 0);
    // 3. gT[b][h,t] = sum_c g_w[h,c] x[b,t,c] + g_b[h]  (M=1024, N=2048, K=2048) — SPLIT
    gemm_mma<1><<<dim3(TT / 128, CHID / 128, BB), 256, GSM_BYTES>>>(
        g_w, x, gT, nullptr, g_b, nullptr,
        CIN, CIN, CIN, TT, 0, (long long)TT * CIN, (long long)CHID * TT);

    // 4. nssm logits = x x^T per batch (M=N=2048, K=2048) — FAST; then softmax
    gemm_mma<0><<<dim3(TT / 128, TT / 128, BB), 256, GSM_BYTES>>>(
        x, x, nssm, nullptr, nullptr, nullptr,
        CIN, CIN, CIN, TT,
        (long long)TT * CIN, (long long)TT * CIN, (long long)TT * TT);
    softmax_rows<<<BB * TT, 256>>>(nssm);

    // 5. att logits = phi theta^T per batch (K=1024) — FAST; then softmax
    gemm_mma<0><<<dim3(TT / 128, TT / 128, BB), 256, GSM_BYTES>>>(
        phi, theta, att, nullptr, nullptr, nullptr,
        CHID, CHID, CHID, TT,
        (long long)TT * CHID, (long long)TT * CHID, (long long)TT * TT);
    softmax_rows<<<BB * TT, 256>>>(att);

    // 6. moca (batch-interleaved combine) + softmax
    combine_softmax<<<BB * TT, 256>>>(nssm, att, moca, rou_w, rou_b);

    // 7. mocaT (batched fp32 transpose)
    transpose_f32<<<dim3(TT / 32, TT / 32, BB), dim3(32, 8)>>>(
        moca, mT, TT, TT, (long long)TT * TT, (long long)TT * TT);

    // 8. y2[b][s,h] = sum_t mocaT[b][s,t] gT[b][h,t]  (M=2048, N=1024, K=2048) — SPLIT
    gemm_mma<1><<<dim3(CHID / 128, TT / 128, BB), 256, GSM_BYTES>>>(
        mT, gT, y2, nullptr, nullptr, nullptr,
        TT, TT, TT, CHID,
        (long long)TT * TT, (long long)CHID * TT, (long long)TT * CHID);

    // 9. wz = y2 @ w_w^T + w_b + x   (M=8192, N=2048, K=1024) — SPLIT
    gemm_mma<1><<<dim3(CIN / 128, MTOT / 128, 1), 256, GSM_BYTES>>>(
        y2, w_w, wz, w_b, nullptr, x,
        CHID, CHID, CHID, CIN, 0, 0, 0);

    // 10. out = wz @ emb_w^T + emb_b  (M=8192, N=256, K=2048) — SPLIT
    gemm_mma<1><<<dim3(CEMB / 128, MTOT / 128, 1), 256, GSM_BYTES>>>(
        wz, emb_w, out, emb_b, nullptr, nullptr,
        CIN, CIN, CIN, CEMB, 0, 0, 0);
}

// round 5
// speedup vs baseline: 3.6777x; 1.1234x over previous
#include <cuda_runtime.h>
#include <cuda_bf16.h>
#include <math.h>
#include <stdint.h>

#define CIN  2048
#define CHID 1024
#define CEMB 256
#define BB   4
#define TT   2048
#define MTOT (BB * TT)   // 8192

// ---------------- scratch (device globals; allocation-free) ----------------
#define BF_ARR(name, n)  __device__ uint4 name[(n) / 8]
#define F32_ARR(name, n) __device__ uint4 name[(n) / 4]

BF_ARR(g_xh, MTOT * CIN);        BF_ARR(g_xl, MTOT * CIN);
BF_ARR(g_twh, CHID * CIN);       BF_ARR(g_twl, CHID * CIN);
BF_ARR(g_pwh, CHID * CIN);       BF_ARR(g_pwl, CHID * CIN);
BF_ARR(g_gwh, CHID * CIN);       BF_ARR(g_gwl, CHID * CIN);
BF_ARR(g_wwh, CIN * CHID);       BF_ARR(g_wwl, CIN * CHID);
BF_ARR(g_ewh, CEMB * CIN);       BF_ARR(g_ewl, CEMB * CIN);
BF_ARR(g_thh, MTOT * CHID);      BF_ARR(g_thl, MTOT * CHID);
BF_ARR(g_phh, MTOT * CHID);      BF_ARR(g_phl, MTOT * CHID);
BF_ARR(g_gTh, BB * CHID * TT);   BF_ARR(g_gTl, BB * CHID * TT);
BF_ARR(g_y2h, MTOT * CHID);      BF_ARR(g_y2l, MTOT * CHID);
BF_ARR(g_wzh, MTOT * CIN);       BF_ARR(g_wzl, MTOT * CIN);
BF_ARR(g_mTh, BB * TT * TT);     BF_ARR(g_mTl, BB * TT * TT);
F32_ARR(g_nssm, BB * TT * TT);
F32_ARR(g_att,  BB * TT * TT);
F32_ARR(g_moca, BB * TT * TT);

// ---------------- helpers ----------------
__device__ __forceinline__ uint32_t smem_u32(const void* p) {
    uint32_t a;
    asm("{ .reg .u64 t; cvta.to.shared.u64 t, %1; cvt.u32.u64 %0, t; }" : "=r"(a) : "l"(p));
    return a;
}
#define LDSM4(r, a) \
    asm volatile("ldmatrix.sync.aligned.m8n8.x4.shared.b16 {%0,%1,%2,%3}, [%4];" \
        : "=r"((r)[0]), "=r"((r)[1]), "=r"((r)[2]), "=r"((r)[3]) : "r"(a))

__device__ __forceinline__ void mmabf(float* c, const uint32_t* a, const uint32_t* b) {
    asm volatile(
        "mma.sync.aligned.m16n8k16.row.col.f32.bf16.bf16.f32 "
        "{%0,%1,%2,%3}, {%4,%5,%6,%7}, {%8,%9}, {%0,%1,%2,%3};"
        : "+f"(c[0]), "+f"(c[1]), "+f"(c[2]), "+f"(c[3])
        : "r"(a[0]), "r"(a[1]), "r"(a[2]), "r"(a[3]), "r"(b[0]), "r"(b[1]));
}

// ---------- bf16x3 GEMM: C[m,n] = sum_k A[m,k]*B[n,k] (full fp32-ish precision) -----
// Block tile 128(M) x 256(N) x 32(K). 256 threads = 8 warps in 2(M) x 4(N), warp 64x64.
// A,B given as precomputed bf16 hi/lo pairs, K-major. C = Ah*Bh + Ah*Bl + Al*Bh.
// smem rows are 80B stride (32 bf16 payload + pad) -> conflict-free ldmatrix.
#define RSTRIDE 80u
#define SZA 10240u                    // 128 rows * 80B
#define SZB 20480u                    // 256 rows * 80B
#define STAGE (2 * SZA + 2 * SZB)     // Ah, Al, Bh, Bl = 61440
#define GSM_BYTES (2 * STAGE)         // 122880

__global__ __launch_bounds__(256) void gemm_bf3(
    const __nv_bfloat16* __restrict__ Ah, const __nv_bfloat16* __restrict__ Al,
    const __nv_bfloat16* __restrict__ Bh, const __nv_bfloat16* __restrict__ Bl,
    float* __restrict__ outF, __nv_bfloat16* __restrict__ outH, __nv_bfloat16* __restrict__ outL,
    const float* __restrict__ biasCol, const float* __restrict__ biasRow,
    const float* __restrict__ addF,
    int K, int lda, int ldb, int ldc,
    long long sA, long long sB, long long sC)
{
    extern __shared__ char smc[];
    const int tid = threadIdx.x;
    const int lane = tid & 31, warp = tid >> 5;
    const int warpM = (warp >> 2) * 64, warpN = (warp & 3) * 64;
    const int lr = lane >> 2, lc = lane & 3;

    const long long bz = blockIdx.z;
    Ah += bz * sA; Al += bz * sA;
    Bh += bz * sB; Bl += bz * sB;
    const long long co = bz * sC;
    if (outF) outF += co;
    if (outH) { outH += co; outL += co; }
    if (addF) addF += co;

    const int m0 = blockIdx.y * 128, n0 = blockIdx.x * 256;
    const uint32_t sb = smem_u32(smc);

    float acc[4][8][4];
    #pragma unroll
    for (int i = 0; i < 4; i++)
        #pragma unroll
        for (int j = 0; j < 8; j++)
            #pragma unroll
            for (int q = 0; q < 4; q++) acc[i][j][q] = 0.0f;

    const int NK = K >> 5;

    auto issue = [&](int st, int k0) {
        const uint32_t so = sb + (uint32_t)st * STAGE;
        #pragma unroll
        for (int i = 0; i < 2; i++) {
            const int id = i * 256 + tid;
            const int r = id >> 2, c = (id & 3) * 8;
            const __nv_bfloat16* gh = Ah + (size_t)(m0 + r) * lda + k0 + c;
            const __nv_bfloat16* gl = Al + (size_t)(m0 + r) * lda + k0 + c;
            const uint32_t d = so + (uint32_t)r * RSTRIDE + (uint32_t)c * 2u;
            asm volatile("cp.async.cg.shared.global [%0], [%1], 16;" :: "r"(d), "l"(gh));
            asm volatile("cp.async.cg.shared.global [%0], [%1], 16;" :: "r"(d + SZA), "l"(gl));
        }
        #pragma unroll
        for (int i = 0; i < 4; i++) {
            const int id = i * 256 + tid;
            const int r = id >> 2, c = (id & 3) * 8;
            const __nv_bfloat16* gh = Bh + (size_t)(n0 + r) * ldb + k0 + c;
            const __nv_bfloat16* gl = Bl + (size_t)(n0 + r) * ldb + k0 + c;
            const uint32_t d = so + 2 * SZA + (uint32_t)r * RSTRIDE + (uint32_t)c * 2u;
            asm volatile("cp.async.cg.shared.global [%0], [%1], 16;" :: "r"(d), "l"(gh));
            asm volatile("cp.async.cg.shared.global [%0], [%1], 16;" :: "r"(d + SZB), "l"(gl));
        }
        asm volatile("cp.async.commit_group;" ::: "memory");
    };

    issue(0, 0);
    for (int kc = 0; kc < NK; kc++) {
        if (kc + 1 < NK) {
            issue((kc + 1) & 1, (kc + 1) << 5);
            asm volatile("cp.async.wait_group 1;" ::: "memory");
        } else {
            asm volatile("cp.async.wait_group 0;" ::: "memory");
        }
        __syncthreads();

        const uint32_t sAst = sb + (uint32_t)(kc & 1) * STAGE;
        const uint32_t sBst = sAst + 2 * SZA;

        #pragma unroll
        for (int kk = 0; kk < 2; kk++) {
            uint32_t af[2][4][4];   // [hi/lo][mt][regs]
            const uint32_t abase = sAst
                + (uint32_t)(warpM + (lane & 15)) * RSTRIDE
                + (uint32_t)(kk * 16 + ((lane >> 4) << 3)) * 2u;
            #pragma unroll
            for (int mt = 0; mt < 4; mt++) {
                LDSM4(af[0][mt], abase + (uint32_t)mt * (16u * RSTRIDE));
                LDSM4(af[1][mt], abase + SZA + (uint32_t)mt * (16u * RSTRIDE));
            }
            #pragma unroll
            for (int p = 0; p < 4; p++) {
                const uint32_t bbase = sBst
                    + (uint32_t)(warpN + p * 16 + ((lane >> 4) << 3) + (lane & 7)) * RSTRIDE
                    + (uint32_t)(kk * 16 + ((lane >> 3) & 1) * 8) * 2u;
                uint32_t bh[4], bl[4];
                LDSM4(bh, bbase);
                LDSM4(bl, bbase + SZB);
                #pragma unroll
                for (int mt = 0; mt < 4; mt++) {
                    #pragma unroll
                    for (int q = 0; q < 2; q++) {
                        float* c = acc[mt][2 * p + q];
                        mmabf(c, af[0][mt], bh + 2 * q);
                        mmabf(c, af[0][mt], bl + 2 * q);
                        mmabf(c, af[1][mt], bh + 2 * q);
                    }
                }
            }
        }
        __syncthreads();
    }

    // epilogue
    #pragma unroll
    for (int mt = 0; mt < 4; mt++) {
        #pragma unroll
        for (int nt = 0; nt < 8; nt++) {
            const int r0 = m0 + warpM + mt * 16 + lr;
            const int r1 = r0 + 8;
            const int cx = n0 + warpN + nt * 8 + 2 * lc;
            float v0 = acc[mt][nt][0], v1 = acc[mt][nt][1];
            float v2 = acc[mt][nt][2], v3 = acc[mt][nt][3];
            if (biasCol) {
                const float b0 = biasCol[cx], b1 = biasCol[cx + 1];
                v0 += b0; v1 += b1; v2 += b0; v3 += b1;
            }
            if (biasRow) { v0 += biasRow[r0]; v1 += biasRow[r0]; v2 += biasRow[r1]; v3 += biasRow[r1]; }
            const size_t o0 = (size_t)r0 * ldc + cx;
            const size_t o1 = (size_t)r1 * ldc + cx;
            if (addF) { v0 += addF[o0]; v1 += addF[o0 + 1]; v2 += addF[o1]; v3 += addF[o1 + 1]; }
            if (outF) {
                float2 w0; w0.x = v0; w0.y = v1;
                float2 w1; w1.x = v2; w1.y = v3;
                *(float2*)&outF[o0] = w0;
                *(float2*)&outF[o1] = w1;
            }
            if (outH) {
                const __nv_bfloat16 h0 = __float2bfloat16(v0), h1 = __float2bfloat16(v1);
                const __nv_bfloat16 h2 = __float2bfloat16(v2), h3 = __float2bfloat16(v3);
                *(__nv_bfloat162*)&outH[o0] = __halves2bfloat162(h0, h1);
                *(__nv_bfloat162*)&outH[o1] = __halves2bfloat162(h2, h3);
                *(__nv_bfloat162*)&outL[o0] = __halves2bfloat162(
                    __float2bfloat16(v0 - __bfloat162float(h0)),
                    __float2bfloat16(v1 - __bfloat162float(h1)));
                *(__nv_bfloat162*)&outL[o1] = __halves2bfloat162(
                    __float2bfloat16(v2 - __bfloat162float(h2)),
                    __float2bfloat16(v3 - __bfloat162float(h3)));
            }
        }
    }
}

// ---------------- fp32 -> bf16 hi/lo split ----------------
__global__ __launch_bounds__(256) void cvt_hilo(
    const float* __restrict__ in, __nv_bfloat16* __restrict__ oh,
    __nv_bfloat16* __restrict__ ol, int n4)
{
    const int i = blockIdx.x * blockDim.x + threadIdx.x;
    if (i >= n4) return;
    const float4 v = ((const float4*)in)[i];
    __nv_bfloat16 h0 = __float2bfloat16(v.x), h1 = __float2bfloat16(v.y);
    __nv_bfloat16 h2 = __float2bfloat16(v.z), h3 = __float2bfloat16(v.w);
    ((__nv_bfloat162*)oh)[2 * i]     = __halves2bfloat162(h0, h1);
    ((__nv_bfloat162*)oh)[2 * i + 1] = __halves2bfloat162(h2, h3);
    ((__nv_bfloat162*)ol)[2 * i] = __halves2bfloat162(
        __float2bfloat16(v.x - __bfloat162float(h0)),
        __float2bfloat16(v.y - __bfloat162float(h1)));
    ((__nv_bfloat162*)ol)[2 * i + 1] = __halves2bfloat162(
        __float2bfloat16(v.z - __bfloat162float(h2)),
        __float2bfloat16(v.w - __bfloat162float(h3)));
}

// -------- batched transpose + hi/lo split: out[c][r] = in[r][c] ------------
__global__ __launch_bounds__(256) void tconv(
    const float* __restrict__ in, __nv_bfloat16* __restrict__ oh,
    __nv_bfloat16* __restrict__ ol, int R, int C, long long sIn, long long sOut)
{
    __shared__ float t[32][33];
    const long long b = blockIdx.z;
    in += b * sIn; oh += b * sOut; ol += b * sOut;
    const int c0 = blockIdx.x * 32, r0 = blockIdx.y * 32;
    const int tx = threadIdx.x, ty = threadIdx.y;
    #pragma unroll
    for (int j = 0; j < 4; j++)
        t[ty + j * 8][tx] = in[(size_t)(r0 + ty + j * 8) * C + (c0 + tx)];
    __syncthreads();
    #pragma unroll
    for (int j = 0; j < 4; j++) {
        const int oc = c0 + ty + j * 8;
        const int orr = r0 + tx;
        const float v = t[tx][ty + j * 8];
        const __nv_bfloat16 h = __float2bfloat16(v);
        oh[(size_t)oc * R + orr] = h;
        ol[(size_t)oc * R + orr] = __float2bfloat16(v - __bfloat162float(h));
    }
}

// ---------------- row softmax over 2048 elements, in place ----------------
__global__ __launch_bounds__(256) void softmax_rows(float* __restrict__ p)
{
    const long long row = blockIdx.x;
    float* r = p + row * (long long)TT;
    const int tid = threadIdx.x;
    float v[8];
    float mx = -3.0e38f;
    #pragma unroll
    for (int i = 0; i < 8; i++) { v[i] = r[tid + i * 256]; mx = fmaxf(mx, v[i]); }
    __shared__ float sm[256];
    sm[tid] = mx; __syncthreads();
    #pragma unroll
    for (int s = 128; s > 0; s >>= 1) {
        if (tid < s) sm[tid] = fmaxf(sm[tid], sm[tid + s]);
        __syncthreads();
    }
    mx = sm[0]; __syncthreads();
    float sum = 0.0f;
    #pragma unroll
    for (int i = 0; i < 8; i++) { v[i] = expf(v[i] - mx); sum += v[i]; }
    sm[tid] = sum; __syncthreads();
    #pragma unroll
    for (int s = 128; s > 0; s >>= 1) {
        if (tid < s) sm[tid] += sm[tid + s];
        __syncthreads();
    }
    const float inv = 1.0f / sm[0];
    #pragma unroll
    for (int i = 0; i < 8; i++) r[tid + i * 256] = v[i] * inv;
}

// ------- cat(axis=0).reshape(B,2,T,T) pairing + combine + softmax ----------
__global__ __launch_bounds__(256) void combine_softmax(
    const float* __restrict__ nssm, const float* __restrict__ att,
    float* __restrict__ moca,
    const float* __restrict__ rou_w, const float* __restrict__ rou_b)
{
    const long long row = blockIdx.x;           // 0 .. B*T-1
    const int b = (int)(row / TT);
    const long long t = row % TT;
    const float r0 = rou_w[0], r1 = rou_w[1], rb = rou_b[0];

    const float* src = (b < 2) ? nssm : att;
    const int base = (b & 1) * 2;
    const float* pa = src + ((long long)base * TT + t) * TT;
    const float* pb = src + ((long long)(base + 1) * TT + t) * TT;
    float* w = moca + row * (long long)TT;

    const int tid = threadIdx.x;
    float v[8];
    float mx = -3.0e38f;
    #pragma unroll
    for (int i = 0; i < 8; i++) {
        const int c = tid + i * 256;
        v[i] = r0 * pa[c] + r1 * pb[c] + rb;
        mx = fmaxf(mx, v[i]);
    }
    __shared__ float sm[256];
    sm[tid] = mx; __syncthreads();
    #pragma unroll
    for (int s = 128; s > 0; s >>= 1) {
        if (tid < s) sm[tid] = fmaxf(sm[tid], sm[tid + s]);
        __syncthreads();
    }
    mx = sm[0]; __syncthreads();
    float sum = 0.0f;
    #pragma unroll
    for (int i = 0; i < 8; i++) { v[i] = expf(v[i] - mx); sum += v[i]; }
    sm[tid] = sum; __syncthreads();
    #pragma unroll
    for (int s = 128; s > 0; s >>= 1) {
        if (tid < s) sm[tid] += sm[tid + s];
        __syncthreads();
    }
    const float inv = 1.0f / sm[0];
    #pragma unroll
    for (int i = 0; i < 8; i++) w[tid + i * 256] = v[i] * inv;
}

// ---------------- launch ----------------
#define SYMF(p, s)  do { void* _t; cudaGetSymbolAddress(&_t, s); p = (float*)_t; } while (0)
#define SYMB(p, s)  do { void* _t; cudaGetSymbolAddress(&_t, s); p = (__nv_bfloat16*)_t; } while (0)

extern "C" void kernel_launch(void* const* d_in, const int* in_sizes, int n_in,
                              void* d_out, int out_size)
{
    (void)in_sizes; (void)n_in; (void)out_size;
    const float* x       = (const float*)d_in[0];
    const float* theta_w = (const float*)d_in[1];
    const float* theta_b = (const float*)d_in[2];
    const float* phi_w   = (const float*)d_in[3];
    const float* phi_b   = (const float*)d_in[4];
    const float* g_w     = (const float*)d_in[5];
    const float* g_b     = (const float*)d_in[6];
    const float* rou_w   = (const float*)d_in[7];
    const float* rou_b   = (const float*)d_in[8];
    const float* w_w     = (const float*)d_in[9];
    const float* w_b     = (const float*)d_in[10];
    const float* emb_w   = (const float*)d_in[11];
    const float* emb_b   = (const float*)d_in[12];
    float* out = (float*)d_out;

    __nv_bfloat16 *xh, *xl, *twh, *twl, *pwh, *pwl, *gwh, *gwl, *wwh, *wwl, *ewh, *ewl;
    __nv_bfloat16 *thh, *thl, *phh, *phl, *gTh, *gTl, *y2h, *y2l, *wzh, *wzl, *mTh, *mTl;
    float *nssm, *att, *moca;
    SYMB(xh, g_xh);   SYMB(xl, g_xl);
    SYMB(twh, g_twh); SYMB(twl, g_twl);
    SYMB(pwh, g_pwh); SYMB(pwl, g_pwl);
    SYMB(gwh, g_gwh); SYMB(gwl, g_gwl);
    SYMB(wwh, g_wwh); SYMB(wwl, g_wwl);
    SYMB(ewh, g_ewh); SYMB(ewl, g_ewl);
    SYMB(thh, g_thh); SYMB(thl, g_thl);
    SYMB(phh, g_phh); SYMB(phl, g_phl);
    SYMB(gTh, g_gTh); SYMB(gTl, g_gTl);
    SYMB(y2h, g_y2h); SYMB(y2l, g_y2l);
    SYMB(wzh, g_wzh); SYMB(wzl, g_wzl);
    SYMB(mTh, g_mTh); SYMB(mTl, g_mTl);
    SYMF(nssm, g_nssm); SYMF(att, g_att); SYMF(moca, g_moca);

    cudaFuncSetAttribute(gemm_bf3, cudaFuncAttributeMaxDynamicSharedMemorySize, GSM_BYTES);

    // 0. hi/lo conversions of x and weights
    cvt_hilo<<<MTOT * CIN / 4 / 256, 256>>>(x, xh, xl, MTOT * CIN / 4);
    cvt_hilo<<<CHID * CIN / 4 / 256, 256>>>(theta_w, twh, twl, CHID * CIN / 4);
    cvt_hilo<<<CHID * CIN / 4 / 256, 256>>>(phi_w, pwh, pwl, CHID * CIN / 4);
    cvt_hilo<<<CHID * CIN / 4 / 256, 256>>>(g_w, gwh, gwl, CHID * CIN / 4);
    cvt_hilo<<<CIN * CHID / 4 / 256, 256>>>(w_w, wwh, wwl, CIN * CHID / 4);
    cvt_hilo<<<CEMB * CIN / 4 / 256, 256>>>(emb_w, ewh, ewl, CEMB * CIN / 4);

    // 1. theta = x @ theta_w^T + theta_b -> hi/lo  (M=8192, N=1024, K=2048)
    gemm_bf3<<<dim3(CHID / 256, MTOT / 128, 1), 256, GSM_BYTES>>>(
        xh, xl, twh, twl, nullptr, thh, thl, theta_b, nullptr, nullptr,
        CIN, CIN, CIN, CHID, 0, 0, 0);
    // 2. phi
    gemm_bf3<<<dim3(CHID / 256, MTOT / 128, 1), 256, GSM_BYTES>>>(
        xh, xl, pwh, pwl, nullptr, phh, phl, phi_b, nullptr, nullptr,
        CIN, CIN, CIN, CHID, 0, 0, 0);
    // 3. gT[b][h,t] = sum_c g_w[h,c] x[b,t,c] + g_b[h]  (M=1024, N=2048, K=2048)
    gemm_bf3<<<dim3(TT / 256, CHID / 128, BB), 256, GSM_BYTES>>>(
        gwh, gwl, xh, xl, nullptr, gTh, gTl, nullptr, g_b, nullptr,
        CIN, CIN, CIN, TT, 0, (long long)TT * CIN, (long long)CHID * TT);

    // 4. nssm logits = x x^T per batch (M=N=2048, K=2048) -> fp32; softmax
    gemm_bf3<<<dim3(TT / 256, TT / 128, BB), 256, GSM_BYTES>>>(
        xh, xl, xh, xl, nssm, nullptr, nullptr, nullptr, nullptr, nullptr,
        CIN, CIN, CIN, TT,
        (long long)TT * CIN, (long long)TT * CIN, (long long)TT * TT);
    softmax_rows<<<BB * TT, 256>>>(nssm);

    // 5. att logits = phi theta^T per batch (K=1024) -> fp32; softmax
    gemm_bf3<<<dim3(TT / 256, TT / 128, BB), 256, GSM_BYTES>>>(
        phh, phl, thh, thl, att, nullptr, nullptr, nullptr, nullptr, nullptr,
        CHID, CHID, CHID, TT,
        (long long)TT * CHID, (long long)TT * CHID, (long long)TT * TT);
    softmax_rows<<<BB * TT, 256>>>(att);

    // 6. moca (batch-interleaved combine) + softmax
    combine_softmax<<<BB * TT, 256>>>(nssm, att, moca, rou_w, rou_b);

    // 7. mocaT hi/lo (batched transpose + split)
    tconv<<<dim3(TT / 32, TT / 32, BB), dim3(32, 8)>>>(
        moca, mTh, mTl, TT, TT, (long long)TT * TT, (long long)TT * TT);

    // 8. y2[b][s,h] = sum_t mocaT[b][s,t] gT[b][h,t]  (M=2048, N=1024, K=2048)
    gemm_bf3<<<dim3(CHID / 256, TT / 128, BB), 256, GSM_BYTES>>>(
        mTh, mTl, gTh, gTl, nullptr, y2h, y2l, nullptr, nullptr, nullptr,
        TT, TT, TT, CHID,
        (long long)TT * TT, (long long)CHID * TT, (long long)TT * CHID);

    // 9. wz = y2 @ w_w^T + w_b + x  (M=8192, N=2048, K=1024) -> hi/lo
    gemm_bf3<<<dim3(CIN / 256, MTOT / 128, 1), 256, GSM_BYTES>>>(
        y2h, y2l, wwh, wwl, nullptr, wzh, wzl, w_b, nullptr, x,
        CHID, CHID, CHID, CIN, 0, 0, 0);

    // 10. out = wz @ emb_w^T + emb_b  (M=8192, N=256, K=2048) -> fp32
    gemm_bf3<<<dim3(CEMB / 256, MTOT / 128, 1), 256, GSM_BYTES>>>(
        wzh, wzl, ewh, ewl, out, nullptr, nullptr, emb_b, nullptr, nullptr,
        CIN, CIN, CIN, CEMB, 0, 0, 0);
}